// round 1
// baseline (speedup 1.0000x reference)
#include <cuda_runtime.h>
#include <math.h>

#define H 256
#define L 256
#define NL 4
#define V 50257

// ---------------- scratch (no allocations allowed) ----------------
__device__ float        g_scores[L];        // attention scores
__device__ float        g_w[L];             // softmax weights
__device__ float        g_ctxp[16 * H];     // partial context sums
__device__ float        g_xbuf[(NL + 1) * H]; // x0 (comb out), h1..h4
__device__ unsigned int g_maxkey;           // encoded max logit
__device__ float        g_sum;              // sum of exp

// monotone float <-> uint key (for atomicMax on floats incl. negatives)
__device__ __forceinline__ unsigned int fkey(float f) {
    unsigned int b = __float_as_uint(f);
    return (b & 0x80000000u) ? ~b : (b | 0x80000000u);
}
__device__ __forceinline__ float fdec(unsigned int k) {
    unsigned int b = (k & 0x80000000u) ? (k & 0x7FFFFFFFu) : ~k;
    return __uint_as_float(b);
}

__device__ __forceinline__ float warp_sum(float v) {
    #pragma unroll
    for (int o = 16; o; o >>= 1) v += __shfl_down_sync(0xFFFFFFFFu, v, o);
    return v;
}

// ---------------- 1) attention scores: 32 blocks, warp per row ----------------
__global__ void k_attn(const int* __restrict__ token, const float* __restrict__ hidden,
                       const float* __restrict__ emb, const float* __restrict__ attn_w,
                       const float* __restrict__ attn_b) {
    __shared__ float s[2 * H];
    int t = threadIdx.x;
    int tok = token[0];
    s[t]     = emb[(long)tok * H + t];
    s[H + t] = hidden[t]; // hidden layer 0
    __syncthreads();
    int w = t >> 5, lane = t & 31;
    int row = blockIdx.x * 8 + w;
    const float4* wr = (const float4*)(attn_w + (long)row * 2 * H);
    float acc = 0.f;
    #pragma unroll
    for (int i = 0; i < 4; i++) {
        float4 q = wr[lane * 4 + i];
        int b = lane * 16 + i * 4;
        acc += q.x * s[b] + q.y * s[b + 1] + q.z * s[b + 2] + q.w * s[b + 3];
    }
    acc = warp_sum(acc);
    if (lane == 0) g_scores[row] = acc + attn_b[row];
}

// ---------------- 2) softmax over 256 scores (1 block) ----------------
__global__ void k_softmax(float* __restrict__ out) {
    __shared__ float red[256];
    int t = threadIdx.x;
    float v = g_scores[t];
    red[t] = v; __syncthreads();
    #pragma unroll
    for (int o = 128; o; o >>= 1) { if (t < o) red[t] = fmaxf(red[t], red[t + o]); __syncthreads(); }
    float m = red[0]; __syncthreads();
    float e = __expf(v - m);
    red[t] = e; __syncthreads();
    #pragma unroll
    for (int o = 128; o; o >>= 1) { if (t < o) red[t] += red[t + o]; __syncthreads(); }
    float wgt = e / red[0];
    g_w[t] = wgt;
    out[V + NL * H + t] = wgt;              // attn_weights output
    if (t == 0) { g_maxkey = 0u; g_sum = 0.f; } // reset for this replay
}

// ---------------- 3) context partials: 16 blocks, coalesced ----------------
__global__ void k_ctx(const float* __restrict__ enc) {
    int t = threadIdx.x, p = blockIdx.x;
    float acc = 0.f;
    #pragma unroll
    for (int i = 0; i < 16; i++) {
        int l = p * 16 + i;
        acc += g_w[l] * enc[(long)l * H + t];
    }
    g_ctxp[p * H + t] = acc;
}

// ---------------- 4) comb matvec + relu: 32 blocks, warp per row ----------------
__global__ void k_comb(const int* __restrict__ token, const float* __restrict__ emb,
                       const float* __restrict__ comb_w, const float* __restrict__ comb_b) {
    __shared__ float s[2 * H];
    int t = threadIdx.x;
    s[t] = emb[(long)token[0] * H + t];
    float acc = 0.f;
    #pragma unroll
    for (int p = 0; p < 16; p++) acc += g_ctxp[p * H + t];
    s[H + t] = acc;
    __syncthreads();
    int w = t >> 5, lane = t & 31;
    int row = blockIdx.x * 8 + w;
    const float4* wr = (const float4*)(comb_w + (long)row * 2 * H);
    float a = 0.f;
    #pragma unroll
    for (int i = 0; i < 4; i++) {
        float4 q = wr[lane * 4 + i];
        int b = lane * 16 + i * 4;
        a += q.x * s[b] + q.y * s[b + 1] + q.z * s[b + 2] + q.w * s[b + 3];
    }
    a = warp_sum(a);
    if (lane == 0) g_xbuf[row] = fmaxf(a + comb_b[row], 0.f);
}

// ---------------- 5-8) GRU layer: 64 blocks x 4 elems; fused gates ----------------
__global__ void k_gru(int l, const float* __restrict__ hidden,
                      const float* __restrict__ wih, const float* __restrict__ whh,
                      const float* __restrict__ bih, const float* __restrict__ bhh,
                      float* __restrict__ out) {
    __shared__ float xs[H], hs[H];
    __shared__ float dots[24];
    int t = threadIdx.x;
    xs[t] = g_xbuf[l * H + t];
    hs[t] = hidden[l * H + t];
    __syncthreads();
    int w = t >> 5, lane = t & 31;
    const float* WIH = wih + (long)l * 3 * H * H;
    const float* WHH = whh + (long)l * 3 * H * H;
    #pragma unroll
    for (int d = w; d < 24; d += 8) {
        int jl = d / 6, tt = d % 6;
        int row = (tt % 3) * H + blockIdx.x * 4 + jl;
        const float4* wr = (const float4*)((tt < 3 ? WIH : WHH) + (long)row * H);
        const float* vec = tt < 3 ? xs : hs;
        float a = 0.f;
        #pragma unroll
        for (int i = 0; i < 2; i++) {
            float4 q = wr[lane * 2 + i];
            int b = lane * 8 + i * 4;
            a += q.x * vec[b] + q.y * vec[b + 1] + q.z * vec[b + 2] + q.w * vec[b + 3];
        }
        a = warp_sum(a);
        if (lane == 0) dots[d] = a;
    }
    __syncthreads();
    if (t < 4) {
        int j = blockIdx.x * 4 + t;
        const float* BIH = bih + l * 3 * H;
        const float* BHH = bhh + l * 3 * H;
        float ir  = dots[t * 6 + 0] + BIH[j];
        float iz  = dots[t * 6 + 1] + BIH[H + j];
        float inn = dots[t * 6 + 2] + BIH[2 * H + j];
        float hr  = dots[t * 6 + 3] + BHH[j];
        float hz  = dots[t * 6 + 4] + BHH[H + j];
        float hn  = dots[t * 6 + 5] + BHH[2 * H + j];
        float r = 1.f / (1.f + __expf(-(ir + hr)));
        float z = 1.f / (1.f + __expf(-(iz + hz)));
        float n = tanhf(inn + r * hn);
        float hnew = (1.f - z) * n + z * hs[j];
        g_xbuf[(l + 1) * H + j] = hnew;
        out[V + l * H + j] = hnew;          // hidden_new output
    }
}

// ---------------- 9) logits: 786 blocks, warp does 8 rows ----------------
__global__ void k_logits(const float* __restrict__ out_w, const float* __restrict__ out_b,
                         float* __restrict__ out) {
    __shared__ float xs[H];
    __shared__ float wmax[8];
    int t = threadIdx.x;
    xs[t] = g_xbuf[NL * H + t];
    __syncthreads();
    int w = t >> 5, lane = t & 31;
    int gw = blockIdx.x * 8 + w;
    float lmax = -3.0e38f;
    #pragma unroll
    for (int rr = 0; rr < 8; rr++) {
        int row = gw * 8 + rr;
        if (row < V) {
            const float4* wr = (const float4*)(out_w + (long)row * H);
            float a = 0.f;
            #pragma unroll
            for (int i = 0; i < 2; i++) {
                float4 q = wr[lane * 2 + i];
                int b = lane * 8 + i * 4;
                a += q.x * xs[b] + q.y * xs[b + 1] + q.z * xs[b + 2] + q.w * xs[b + 3];
            }
            a = warp_sum(a);
            if (lane == 0) {
                a += out_b[row];
                out[row] = a;
                lmax = fmaxf(lmax, a);
            }
        }
    }
    if (lane == 0) wmax[w] = lmax;
    __syncthreads();
    if (t == 0) {
        float m = wmax[0];
        #pragma unroll
        for (int i = 1; i < 8; i++) m = fmaxf(m, wmax[i]);
        atomicMax(&g_maxkey, fkey(m));
    }
}

// ---------------- 10) sum of exp ----------------
__global__ void k_sumexp(const float* __restrict__ out) {
    __shared__ float red[256];
    int t = threadIdx.x;
    float m = fdec(g_maxkey);
    float s = 0.f;
    for (int v = blockIdx.x * 256 + t; v < V; v += 64 * 256)
        s += __expf(out[v] - m);
    red[t] = s; __syncthreads();
    #pragma unroll
    for (int o = 128; o; o >>= 1) { if (t < o) red[t] += red[t + o]; __syncthreads(); }
    if (t == 0) atomicAdd(&g_sum, red[0]);
}

// ---------------- 11) finalize log_softmax in place ----------------
__global__ void k_final(float* __restrict__ out) {
    float m = fdec(g_maxkey);
    float ls = logf(g_sum);
    for (int v = blockIdx.x * 256 + threadIdx.x; v < V; v += 64 * 256)
        out[v] = out[v] - m - ls;
}

extern "C" void kernel_launch(void* const* d_in, const int* in_sizes, int n_in,
                              void* d_out, int out_size) {
    const int*   token  = (const int*)d_in[0];
    const float* hidden = (const float*)d_in[1];
    const float* enc    = (const float*)d_in[2];
    const float* emb    = (const float*)d_in[3];
    const float* attn_w = (const float*)d_in[4];
    const float* attn_b = (const float*)d_in[5];
    const float* comb_w = (const float*)d_in[6];
    const float* comb_b = (const float*)d_in[7];
    const float* wih    = (const float*)d_in[8];
    const float* whh    = (const float*)d_in[9];
    const float* bih    = (const float*)d_in[10];
    const float* bhh    = (const float*)d_in[11];
    const float* out_w  = (const float*)d_in[12];
    const float* out_b  = (const float*)d_in[13];
    float* out = (float*)d_out;

    k_attn<<<32, 256>>>(token, hidden, emb, attn_w, attn_b);
    k_softmax<<<1, 256>>>(out);
    k_ctx<<<16, 256>>>(enc);
    k_comb<<<32, 256>>>(token, emb, comb_w, comb_b);
    for (int l = 0; l < NL; l++)
        k_gru<<<64, 256>>>(l, hidden, wih, whh, bih, bhh, out);
    k_logits<<<786, 256>>>(out_w, out_b, out);
    k_sumexp<<<64, 256>>>(out);
    k_final<<<64, 256>>>(out);
}

// round 2
// speedup vs baseline: 1.1882x; 1.1882x over previous
#include <cuda_runtime.h>
#include <math.h>

#define H 256
#define L 256
#define NL 4
#define V 50257

// ---------------- scratch (no allocations allowed) ----------------
__device__ float        g_scores[L];          // attention scores
__device__ float        g_ctxp[32 * H];       // partial context sums
__device__ float        g_xbuf[(NL + 1) * H]; // x0 (comb out), h1..h4
__device__ unsigned int g_maxkey;             // encoded max logit
__device__ float        g_sum;                // sum of exp

// monotone float <-> uint key (for atomicMax on floats incl. negatives)
__device__ __forceinline__ unsigned int fkey(float f) {
    unsigned int b = __float_as_uint(f);
    return (b & 0x80000000u) ? ~b : (b | 0x80000000u);
}
__device__ __forceinline__ float fdec(unsigned int k) {
    unsigned int b = (k & 0x80000000u) ? (k & 0x7FFFFFFFu) : ~k;
    return __uint_as_float(b);
}

__device__ __forceinline__ float warp_sum(float v) {
    #pragma unroll
    for (int o = 16; o; o >>= 1) v += __shfl_down_sync(0xFFFFFFFFu, v, o);
    return v;
}

// ---------------- 1) attention scores: 64 blocks x 128 thr, warp per row --------
__global__ void k_attn(const int* __restrict__ token, const float* __restrict__ hidden,
                       const float* __restrict__ emb, const float* __restrict__ attn_w,
                       const float* __restrict__ attn_b) {
    __shared__ float s[2 * H];
    int t = threadIdx.x;
    int tok = token[0];
    // s[0..255] = embedded, s[256..511] = hidden[0]
    s[t]       = emb[(long)tok * H + t];
    s[t + 128] = emb[(long)tok * H + t + 128];
    s[t + 256] = hidden[t];
    s[t + 384] = hidden[t + 128];
    __syncthreads();
    int w = t >> 5, lane = t & 31;
    int row = blockIdx.x * 4 + w;
    const float4* wr = (const float4*)(attn_w + (long)row * 2 * H);
    float4 q[4];
    #pragma unroll
    for (int i = 0; i < 4; i++) q[i] = wr[lane + 32 * i];   // all loads in flight
    float acc = 0.f;
    #pragma unroll
    for (int i = 0; i < 4; i++) {
        int b = 4 * (lane + 32 * i);
        acc += q[i].x * s[b] + q[i].y * s[b + 1] + q[i].z * s[b + 2] + q[i].w * s[b + 3];
    }
    acc = warp_sum(acc);
    if (lane == 0) g_scores[row] = acc + attn_b[row];
    if (blockIdx.x == 0 && t == 0) { g_maxkey = 0u; g_sum = 0.f; } // replay reset
}

// ---------- 2) fused softmax (redundant per block) + context partials: 32 blocks -
__global__ void k_ctxsm(const float* __restrict__ enc, float* __restrict__ out) {
    __shared__ float red[256];
    __shared__ float sw[256];
    int t = threadIdx.x;
    float v = g_scores[t];
    red[t] = v; __syncthreads();
    #pragma unroll
    for (int o = 128; o; o >>= 1) { if (t < o) red[t] = fmaxf(red[t], red[t + o]); __syncthreads(); }
    float m = red[0]; __syncthreads();
    float e = __expf(v - m);
    red[t] = e; __syncthreads();
    #pragma unroll
    for (int o = 128; o; o >>= 1) { if (t < o) red[t] += red[t + o]; __syncthreads(); }
    float wgt = e / red[0];
    sw[t] = wgt;
    if (blockIdx.x == 0) out[V + NL * H + t] = wgt;  // attn_weights output
    __syncthreads();
    int p = blockIdx.x;
    float acc = 0.f;
    #pragma unroll
    for (int i = 0; i < 8; i++) {
        int l = p * 8 + i;
        acc += sw[l] * enc[(long)l * H + t];
    }
    g_ctxp[p * H + t] = acc;
}

// ---------------- 3) comb matvec + relu: 64 blocks x 128 thr, warp per row ------
__global__ void k_comb(const int* __restrict__ token, const float* __restrict__ emb,
                       const float* __restrict__ comb_w, const float* __restrict__ comb_b) {
    __shared__ float s[2 * H];
    int t = threadIdx.x;
    int tok = token[0];
    s[t]       = emb[(long)tok * H + t];
    s[t + 128] = emb[(long)tok * H + t + 128];
    float a0 = 0.f, a1 = 0.f;
    #pragma unroll
    for (int p = 0; p < 32; p++) {
        a0 += g_ctxp[p * H + t];
        a1 += g_ctxp[p * H + t + 128];
    }
    s[t + 256] = a0;
    s[t + 384] = a1;
    __syncthreads();
    int w = t >> 5, lane = t & 31;
    int row = blockIdx.x * 4 + w;
    const float4* wr = (const float4*)(comb_w + (long)row * 2 * H);
    float4 q[4];
    #pragma unroll
    for (int i = 0; i < 4; i++) q[i] = wr[lane + 32 * i];
    float acc = 0.f;
    #pragma unroll
    for (int i = 0; i < 4; i++) {
        int b = 4 * (lane + 32 * i);
        acc += q[i].x * s[b] + q[i].y * s[b + 1] + q[i].z * s[b + 2] + q[i].w * s[b + 3];
    }
    acc = warp_sum(acc);
    if (lane == 0) g_xbuf[row] = fmaxf(acc + comb_b[row], 0.f);
}

// ------- 4-7) GRU layer: 128 blocks x 128 thr, 2 elems/block, 3 dots/warp -------
__global__ void k_gru(int l, const float* __restrict__ hidden,
                      const float* __restrict__ wih, const float* __restrict__ whh,
                      const float* __restrict__ bih, const float* __restrict__ bhh,
                      float* __restrict__ out) {
    __shared__ float xs[H], hs[H];
    __shared__ float dots[12];
    int t = threadIdx.x;
    xs[t]       = g_xbuf[l * H + t];
    xs[t + 128] = g_xbuf[l * H + t + 128];
    hs[t]       = hidden[l * H + t];
    hs[t + 128] = hidden[l * H + t + 128];
    __syncthreads();
    int w = t >> 5, lane = t & 31;
    const float* WIH = wih + (long)l * 3 * H * H;
    const float* WHH = whh + (long)l * 3 * H * H;
    // 12 dots: d = e*6 + tt (e=elem 0..1, tt: 0..2 ih r/z/n, 3..5 hh r/z/n)
    float4 q[3][2];
    const float* vecs[3];
    #pragma unroll
    for (int k = 0; k < 3; k++) {
        int d = w + 4 * k;
        int e = d / 6, tt = d % 6;
        int j = blockIdx.x * 2 + e;
        int row = (tt % 3) * H + j;
        const float4* wr = (const float4*)((tt < 3 ? WIH : WHH) + (long)row * H);
        vecs[k] = (tt < 3) ? xs : hs;
        q[k][0] = wr[lane];
        q[k][1] = wr[lane + 32];
    }
    #pragma unroll
    for (int k = 0; k < 3; k++) {
        float a = 0.f;
        #pragma unroll
        for (int i = 0; i < 2; i++) {
            int b = 4 * (lane + 32 * i);
            const float* vv = vecs[k];
            a += q[k][i].x * vv[b] + q[k][i].y * vv[b + 1] + q[k][i].z * vv[b + 2] + q[k][i].w * vv[b + 3];
        }
        a = warp_sum(a);
        if (lane == 0) dots[w + 4 * k] = a;
    }
    __syncthreads();
    if (t < 2) {
        int j = blockIdx.x * 2 + t;
        const float* BIH = bih + l * 3 * H;
        const float* BHH = bhh + l * 3 * H;
        float ir  = dots[t * 6 + 0] + BIH[j];
        float iz  = dots[t * 6 + 1] + BIH[H + j];
        float inn = dots[t * 6 + 2] + BIH[2 * H + j];
        float hr  = dots[t * 6 + 3] + BHH[j];
        float hz  = dots[t * 6 + 4] + BHH[H + j];
        float hn  = dots[t * 6 + 5] + BHH[2 * H + j];
        float r = 1.f / (1.f + __expf(-(ir + hr)));
        float z = 1.f / (1.f + __expf(-(iz + hz)));
        float n = tanhf(inn + r * hn);
        float hnew = (1.f - z) * n + z * hs[j];
        g_xbuf[(l + 1) * H + j] = hnew;
        out[V + l * H + j] = hnew;          // hidden_new output
    }
}

// -------- 8) logits: 786 blocks x 256 thr; 8 rows/warp, 4 lanes/row, MLP=16 -----
__global__ void k_logits(const float* __restrict__ out_w, const float* __restrict__ out_b,
                         float* __restrict__ out) {
    __shared__ float xs[H];
    __shared__ float wmax[8];
    int t = threadIdx.x;
    xs[t] = g_xbuf[NL * H + t];
    __syncthreads();
    int w = t >> 5, lane = t & 31;
    int g = lane >> 2;           // row within warp's group of 8
    int sl = lane & 3;           // sub-lane within row
    int row = (blockIdx.x * 8 + w) * 8 + g;
    bool valid = row < V;
    const float4* wr = (const float4*)(out_w + (long)row * H);
    float4 q[16];
    if (valid) {
        #pragma unroll
        for (int i = 0; i < 16; i++) q[i] = wr[sl + 4 * i];   // 16 independent loads
    } else {
        #pragma unroll
        for (int i = 0; i < 16; i++) q[i] = make_float4(0.f, 0.f, 0.f, 0.f);
    }
    float acc = 0.f;
    #pragma unroll
    for (int i = 0; i < 16; i++) {
        int b = 4 * (sl + 4 * i);
        acc += q[i].x * xs[b] + q[i].y * xs[b + 1] + q[i].z * xs[b + 2] + q[i].w * xs[b + 3];
    }
    // reduce over the 4 lanes of this row (butterfly -> all 4 lanes hold sum)
    acc += __shfl_xor_sync(0xFFFFFFFFu, acc, 2);
    acc += __shfl_xor_sync(0xFFFFFFFFu, acc, 1);
    float a = valid ? acc + out_b[row] : -3.0e38f;
    if (valid && sl == 0) out[row] = a;
    // warp-wide max over all 8 rows
    float m = a;
    #pragma unroll
    for (int o = 16; o; o >>= 1) m = fmaxf(m, __shfl_down_sync(0xFFFFFFFFu, m, o));
    if (lane == 0) wmax[w] = m;
    __syncthreads();
    if (t == 0) {
        float mm = wmax[0];
        #pragma unroll
        for (int i = 1; i < 8; i++) mm = fmaxf(mm, wmax[i]);
        atomicMax(&g_maxkey, fkey(mm));
    }
}

// ---------------- 9) sum of exp: one element per thread ----------------
__global__ void k_sumexp(const float* __restrict__ out) {
    __shared__ float red[256];
    int t = threadIdx.x;
    int v = blockIdx.x * 256 + t;
    float m = fdec(g_maxkey);
    red[t] = (v < V) ? __expf(out[v] - m) : 0.f;
    __syncthreads();
    #pragma unroll
    for (int o = 128; o; o >>= 1) { if (t < o) red[t] += red[t + o]; __syncthreads(); }
    if (t == 0) atomicAdd(&g_sum, red[0]);
}

// ---------------- 10) finalize log_softmax in place ----------------
__global__ void k_final(float* __restrict__ out) {
    int v = blockIdx.x * 256 + threadIdx.x;
    if (v < V) {
        float m = fdec(g_maxkey);
        float ls = logf(g_sum);
        out[v] = out[v] - m - ls;
    }
}

extern "C" void kernel_launch(void* const* d_in, const int* in_sizes, int n_in,
                              void* d_out, int out_size) {
    const int*   token  = (const int*)d_in[0];
    const float* hidden = (const float*)d_in[1];
    const float* enc    = (const float*)d_in[2];
    const float* emb    = (const float*)d_in[3];
    const float* attn_w = (const float*)d_in[4];
    const float* attn_b = (const float*)d_in[5];
    const float* comb_w = (const float*)d_in[6];
    const float* comb_b = (const float*)d_in[7];
    const float* wih    = (const float*)d_in[8];
    const float* whh    = (const float*)d_in[9];
    const float* bih    = (const float*)d_in[10];
    const float* bhh    = (const float*)d_in[11];
    const float* out_w  = (const float*)d_in[12];
    const float* out_b  = (const float*)d_in[13];
    float* out = (float*)d_out;

    k_attn<<<64, 128>>>(token, hidden, emb, attn_w, attn_b);
    k_ctxsm<<<32, 256>>>(enc, out);
    k_comb<<<64, 128>>>(token, emb, comb_w, comb_b);
    for (int l = 0; l < NL; l++)
        k_gru<<<128, 128>>>(l, hidden, wih, whh, bih, bhh, out);
    k_logits<<<786, 256>>>(out_w, out_b, out);
    k_sumexp<<<197, 256>>>(out);
    k_final<<<197, 256>>>(out);
}